// round 6
// baseline (speedup 1.0000x reference)
#include <cuda_runtime.h>
#include <cstdint>

// ---------------------------------------------------------------------------
// TripletLoss, JAX-exact gumbel semi-hard mining. B=384, D=256, C=48.
//
// JAX >= 0.4.36 defaults jax_threefry_partitionable=True. Random bits for a
// float32 tensor of size N are, per flat element n:
//     (o0, o1) = threefry2x32(key=(0,42), counter=(n >> 32, n & 0xffffffff))
//     bits[n]  = o0 ^ o1
// (NOT the legacy split-iota-in-half pairing.) Here N = B^3 < 2^32 so the
// counter is (0, n),  n = (i*B + p)*B + k.
//
// Key insight for speed: neg_idx is only consumed where
// valid = (labels[i]==labels[p]) & (p>i) & has_neg  -> only ~B^2/(2C) ~ 1.5K
// of the 147K (i,p) rows. All gumbel/cipher work is skipped elsewhere.
// ---------------------------------------------------------------------------

#define BB 384
#define DD 256
#define MARGIN 0.2f

__device__ float  g_dist[BB * BB];
__device__ double g_total;
__device__ unsigned int g_count;

// ---------------- Threefry-2x32-20, key = (0, 42) --------------------------
__device__ __forceinline__ void threefry2x32_42(unsigned c0, unsigned c1,
                                                unsigned& o0, unsigned& o1) {
    const unsigned ks0 = 0u;
    const unsigned ks1 = 42u;
    const unsigned ks2 = 0x1BD11BDAu ^ ks0 ^ ks1;
    unsigned x0 = c0 + ks0;
    unsigned x1 = c1 + ks1;
#define TF_ROUND(R) { x0 += x1; x1 = __funnelshift_l(x1, x1, (R)); x1 ^= x0; }
    TF_ROUND(13) TF_ROUND(15) TF_ROUND(26) TF_ROUND(6)
    x0 += ks1; x1 += ks2 + 1u;
    TF_ROUND(17) TF_ROUND(29) TF_ROUND(16) TF_ROUND(24)
    x0 += ks2; x1 += ks0 + 2u;
    TF_ROUND(13) TF_ROUND(15) TF_ROUND(26) TF_ROUND(6)
    x0 += ks0; x1 += ks1 + 3u;
    TF_ROUND(17) TF_ROUND(29) TF_ROUND(16) TF_ROUND(24)
    x0 += ks1; x1 += ks2 + 4u;
    TF_ROUND(13) TF_ROUND(15) TF_ROUND(26) TF_ROUND(6)
    x0 += ks2; x1 += ks0 + 5u;
#undef TF_ROUND
    o0 = x0; o1 = x1;
}

// jax uniform(minval=tiny, maxval=1): f = bitcast((bits>>9)|0x3f800000)-1;
// (maxval-minval)==1 in fp32 and f+tiny rounds to f, so u = max(f, tiny).
// gumbel = -log(-log(u)). Accurate logf (not __logf) for safety.
__device__ __forceinline__ float gumbel_from_bits(unsigned bits) {
    const float tiny = 1.17549435e-38f;
    float f = __uint_as_float((bits >> 9) | 0x3f800000u) - 1.0f;
    float u = fmaxf(f, tiny);
    return -logf(-logf(u));
}

// ---------------- dist kernel (also initializes accumulators) --------------
__global__ __launch_bounds__(256) void dist_kernel(const float* __restrict__ feat) {
    if (blockIdx.x == 0 && blockIdx.y == 0 && threadIdx.x == 0 && threadIdx.y == 0) {
        g_total = 0.0;
        g_count = 0u;
    }
    __shared__ float shI[16][33];
    __shared__ float shJ[16][33];
    const int ti = threadIdx.y, tj = threadIdx.x;
    const int i0 = blockIdx.y * 16, j0 = blockIdx.x * 16;
    const int t = ti * 16 + tj;
    float acc = 0.0f;
    for (int d0 = 0; d0 < DD; d0 += 32) {
        for (int s = t; s < 16 * 32; s += 256) {
            int r = s >> 5, c = s & 31;
            shI[r][c] = feat[(i0 + r) * DD + d0 + c];
            shJ[r][c] = feat[(j0 + r) * DD + d0 + c];
        }
        __syncthreads();
#pragma unroll
        for (int c = 0; c < 32; ++c) {
            float df = shI[ti][c] - shJ[tj][c];
            acc = fmaf(df, df, acc);
        }
        __syncthreads();
    }
    g_dist[(i0 + ti) * BB + (j0 + tj)] = sqrtf(fmaxf(acc, 1e-11f));
}

// ---------------- mining kernel: one warp per (i,p) row; 99% early-exit ----
__global__ __launch_bounds__(256) void triplet_kernel(const int* __restrict__ labels,
                                                      const int* __restrict__ epoch_p) {
    const int r = (int)((blockIdx.x * blockDim.x + threadIdx.x) >> 5);
    const int lane = (int)(threadIdx.x & 31);
    if (r >= BB * BB) return;

    const int i = r / BB;
    const int p = r - i * BB;
    // valid pairs only: same label and p > i (the argmax result is consumed
    // nowhere else in the reference).
    if (p <= i) return;
    const int labi = labels[i];
    if (labi != labels[p]) return;

    const float* __restrict__ drow = g_dist + i * BB;
    const float dp = drow[p];
    const float dhi = dp + MARGIN;
    const bool semiMode = (*epoch_p) > 3;

    float best = -3.4e38f;
    int   bk = 0;
    bool  any = false;
    const unsigned nbase = (unsigned)r * (unsigned)BB;

#pragma unroll 1
    for (int tile = 0; tile < BB / 32; ++tile) {
        const int k = tile * 32 + lane;
        const int labk = labels[k];
        const float dk = drow[k];
        bool s;
        if (semiMode) {
            s = (labk != labi) && (dk > dp) && (dk < dhi);
        } else {
            s = (labk != labi);
        }
        any |= s;
        if (__ballot_sync(0xffffffffu, s)) {
            if (s) {
                unsigned o0, o1;
                threefry2x32_42(0u, nbase + (unsigned)k, o0, o1);
                float sc = (semiMode ? -logf(dk) : 0.0f) + gumbel_from_bits(o0 ^ o1);
                if (sc > best) { best = sc; bk = k; }  // k ascends per lane: first-max kept
            }
        }
    }

    // warp argmax, lowest-index tie-break (matches jnp.argmax)
#pragma unroll
    for (int off = 16; off > 0; off >>= 1) {
        float ov = __shfl_down_sync(0xffffffffu, best, off);
        int   ok = __shfl_down_sync(0xffffffffu, bk,   off);
        if (ov > best || (ov == best && ok < bk)) { best = ov; bk = ok; }
    }
    const unsigned has = __ballot_sync(0xffffffffu, any);

    if (lane == 0 && has) {
        float pp = fmaxf(dp - drow[bk] + MARGIN, 0.0f);
        atomicAdd(&g_total, (double)pp);
        atomicAdd(&g_count, 1u);
    }
}

__global__ void finalize_kernel(float* __restrict__ out) {
    float res = 0.0f;
    unsigned c = g_count;
    if (c > 0u) res = (float)(g_total / (double)c);
    out[0] = res;
}

extern "C" void kernel_launch(void* const* d_in, const int* in_sizes, int n_in,
                              void* d_out, int out_size) {
    const float* feat   = (const float*)d_in[0];
    const int*   labels = (const int*)d_in[1];
    const int*   epoch  = (const int*)d_in[2];
    float*       out    = (float*)d_out;

    dim3 db(16, 16);
    dim3 dg(BB / 16, BB / 16);
    dist_kernel<<<dg, db>>>(feat);

    const int total_threads = BB * BB * 32;   // one warp per (i,p) row
    const int tpb = 256;
    const int blocks = (total_threads + tpb - 1) / tpb;
    triplet_kernel<<<blocks, tpb>>>(labels, epoch);

    finalize_kernel<<<1, 1>>>(out);
}

// round 10
// speedup vs baseline: 1.4768x; 1.4768x over previous
#include <cuda_runtime.h>
#include <cstdint>

// ---------------------------------------------------------------------------
// TripletLoss, JAX-exact gumbel semi-hard mining. B=384, D=256, C=48.
//
// JAX (threefry_partitionable) random bits for a float32 tensor of size N:
//     (o0, o1) = threefry2x32(key=(0,42), counter=(n>>32, n&0xffffffff))
//     bits[n]  = o0 ^ o1
// N = B^3 < 2^32 -> counter = (0, n), n = (i*B + p)*B + k.
//
// Speed structure:
//   kernel 1: 32x32-tiled pairwise distance (2x2 register micro-tiles,
//             float4 gmem loads), also re-inits global accumulators.
//   kernel 2: one block per anchor i; builds the (few) valid positives in
//             smem, one warp mines each; last finished block writes out[0].
// ---------------------------------------------------------------------------

#define BB 384
#define DD 256
#define MARGIN 0.2f

__device__ float  g_dist[BB * BB];
__device__ double g_total;
__device__ unsigned int g_count;
__device__ unsigned int g_done;

// ---------------- Threefry-2x32-20, key = (0, 42) --------------------------
__device__ __forceinline__ void threefry2x32_42(unsigned c0, unsigned c1,
                                                unsigned& o0, unsigned& o1) {
    const unsigned ks0 = 0u;
    const unsigned ks1 = 42u;
    const unsigned ks2 = 0x1BD11BDAu ^ ks0 ^ ks1;
    unsigned x0 = c0 + ks0;
    unsigned x1 = c1 + ks1;
#define TF_ROUND(R) { x0 += x1; x1 = __funnelshift_l(x1, x1, (R)); x1 ^= x0; }
    TF_ROUND(13) TF_ROUND(15) TF_ROUND(26) TF_ROUND(6)
    x0 += ks1; x1 += ks2 + 1u;
    TF_ROUND(17) TF_ROUND(29) TF_ROUND(16) TF_ROUND(24)
    x0 += ks2; x1 += ks0 + 2u;
    TF_ROUND(13) TF_ROUND(15) TF_ROUND(26) TF_ROUND(6)
    x0 += ks0; x1 += ks1 + 3u;
    TF_ROUND(17) TF_ROUND(29) TF_ROUND(16) TF_ROUND(24)
    x0 += ks1; x1 += ks2 + 4u;
    TF_ROUND(13) TF_ROUND(15) TF_ROUND(26) TF_ROUND(6)
    x0 += ks2; x1 += ks0 + 5u;
#undef TF_ROUND
    o0 = x0; o1 = x1;
}

// jax uniform(tiny,1): f = bitcast((bits>>9)|0x3f800000)-1; u = max(f,tiny);
// gumbel = -log(-log(u)). Accurate logf (selection-critical near u->1).
__device__ __forceinline__ float gumbel_from_bits(unsigned bits) {
    const float tiny = 1.17549435e-38f;
    float f = __uint_as_float((bits >> 9) | 0x3f800000u) - 1.0f;
    float u = fmaxf(f, tiny);
    return -logf(-logf(u));
}

// ---------------- dist kernel: 32x32 tile, 2x2 per-thread micro-tile -------
__global__ __launch_bounds__(256) void dist_kernel(const float* __restrict__ feat) {
    if (blockIdx.x == 0 && blockIdx.y == 0 && threadIdx.x == 0) {
        g_total = 0.0;
        g_count = 0u;
        g_done  = 0u;
    }
    __shared__ float shA[32][33];
    __shared__ float shB[32][33];
    const int t  = threadIdx.x;
    const int tx = t & 15;          // 0..15 -> j micro-tile
    const int ty = t >> 4;          // 0..15 -> i micro-tile
    const int i0 = blockIdx.y * 32, j0 = blockIdx.x * 32;
    const int lr = t >> 3;          // load row 0..31
    const int lc = (t & 7) * 4;     // load col 0,4,...,28

    float a00 = 0.f, a01 = 0.f, a10 = 0.f, a11 = 0.f;

    for (int d0 = 0; d0 < DD; d0 += 32) {
        const float4 av = *(const float4*)&feat[(i0 + lr) * DD + d0 + lc];
        const float4 bv = *(const float4*)&feat[(j0 + lr) * DD + d0 + lc];
        shA[lr][lc + 0] = av.x; shA[lr][lc + 1] = av.y;
        shA[lr][lc + 2] = av.z; shA[lr][lc + 3] = av.w;
        shB[lr][lc + 0] = bv.x; shB[lr][lc + 1] = bv.y;
        shB[lr][lc + 2] = bv.z; shB[lr][lc + 3] = bv.w;
        __syncthreads();
#pragma unroll
        for (int kk = 0; kk < 32; ++kk) {
            const float ai0 = shA[2 * ty + 0][kk];
            const float ai1 = shA[2 * ty + 1][kk];
            const float bj0 = shB[2 * tx + 0][kk];
            const float bj1 = shB[2 * tx + 1][kk];
            float d;
            d = ai0 - bj0; a00 = fmaf(d, d, a00);
            d = ai0 - bj1; a01 = fmaf(d, d, a01);
            d = ai1 - bj0; a10 = fmaf(d, d, a10);
            d = ai1 - bj1; a11 = fmaf(d, d, a11);
        }
        __syncthreads();
    }
    const int i = i0 + 2 * ty;
    const int j = j0 + 2 * tx;
    g_dist[(i + 0) * BB + j + 0] = sqrtf(fmaxf(a00, 1e-11f));
    g_dist[(i + 0) * BB + j + 1] = sqrtf(fmaxf(a01, 1e-11f));
    g_dist[(i + 1) * BB + j + 0] = sqrtf(fmaxf(a10, 1e-11f));
    g_dist[(i + 1) * BB + j + 1] = sqrtf(fmaxf(a11, 1e-11f));
}

// ---------------- mining kernel: one block per anchor i --------------------
__global__ __launch_bounds__(384) void mine_kernel(const int* __restrict__ labels,
                                                   const int* __restrict__ epoch_p,
                                                   float* __restrict__ out) {
    __shared__ int   s_lab[BB];
    __shared__ float s_d[BB];
    __shared__ int   s_pos[BB];
    __shared__ int   s_np;
    const int i = blockIdx.x;
    const int t = threadIdx.x;
    const int wid = t >> 5, lane = t & 31;

    if (t == 0) s_np = 0;
    s_lab[t] = labels[t];
    s_d[t]   = g_dist[i * BB + t];
    __syncthreads();

    const int labi = s_lab[i];
    if (t > i && s_lab[t] == labi) {
        int slot = atomicAdd(&s_np, 1);
        s_pos[slot] = t;               // order irrelevant: results are summed
    }
    __syncthreads();

    const int  np = s_np;
    const bool semiMode = (*epoch_p) > 3;

    for (int w = wid; w < np; w += 12) {
        const int   p   = s_pos[w];
        const float dp  = s_d[p];
        const float dhi = dp + MARGIN;
        const unsigned nbase = ((unsigned)i * BB + (unsigned)p) * (unsigned)BB;

        float best = -3.4e38f;
        int   bk   = 0;
        bool  any  = false;
#pragma unroll 1
        for (int tile = 0; tile < BB / 32; ++tile) {
            const int   k  = tile * 32 + lane;
            const float dk = s_d[k];
            bool s;
            if (semiMode) s = (s_lab[k] != labi) && (dk > dp) && (dk < dhi);
            else          s = (s_lab[k] != labi);
            any |= s;
            if (__ballot_sync(0xffffffffu, s)) {
                if (s) {
                    unsigned o0, o1;
                    threefry2x32_42(0u, nbase + (unsigned)k, o0, o1);
                    float sc = (semiMode ? -logf(dk) : 0.0f)
                             + gumbel_from_bits(o0 ^ o1);
                    if (sc > best) { best = sc; bk = k; }  // ascending k: first-max kept
                }
            }
        }
        // warp argmax, lowest-index tie-break (matches jnp.argmax)
#pragma unroll
        for (int off = 16; off > 0; off >>= 1) {
            float ov = __shfl_down_sync(0xffffffffu, best, off);
            int   ok = __shfl_down_sync(0xffffffffu, bk,   off);
            if (ov > best || (ov == best && ok < bk)) { best = ov; bk = ok; }
        }
        const unsigned has = __ballot_sync(0xffffffffu, any);
        if (lane == 0 && has) {
            float pp = fmaxf(dp - s_d[bk] + MARGIN, 0.0f);
            atomicAdd(&g_total, (double)pp);
            atomicAdd(&g_count, 1u);
        }
    }

    // last finished block writes the scalar output
    __syncthreads();
    if (t == 0) {
        __threadfence();
        unsigned old = atomicAdd(&g_done, 1u);
        if (old == gridDim.x - 1) {
            double   tot = atomicAdd(&g_total, 0.0);   // coherent L2 read
            unsigned cnt = atomicAdd(&g_count, 0u);
            out[0] = (cnt > 0u) ? (float)(tot / (double)cnt) : 0.0f;
        }
    }
}

extern "C" void kernel_launch(void* const* d_in, const int* in_sizes, int n_in,
                              void* d_out, int out_size) {
    const float* feat   = (const float*)d_in[0];
    const int*   labels = (const int*)d_in[1];
    const int*   epoch  = (const int*)d_in[2];
    float*       out    = (float*)d_out;

    dim3 dg(BB / 32, BB / 32);          // 12 x 12 = 144 blocks
    dist_kernel<<<dg, 256>>>(feat);

    mine_kernel<<<BB, BB>>>(labels, epoch, out);
}

// round 12
// speedup vs baseline: 1.5508x; 1.0501x over previous
#include <cuda_runtime.h>
#include <cstdint>

// ---------------------------------------------------------------------------
// TripletLoss, JAX-exact gumbel semi-hard mining. B=384, D=256, C=48.
//
// JAX (threefry_partitionable) random bits for a float32 tensor of size N:
//     (o0, o1) = threefry2x32(key=(0,42), counter=(n>>32, n&0xffffffff))
//     bits[n]  = o0 ^ o1
// N = B^3 < 2^32 -> counter = (0, n), n = (i*B + p)*B + k.
//
// Single persistent kernel, 144 blocks x 256 threads (one wave):
//   phase 1: 32x32 dist tile per block (2x2 register micro-tiles, float4).
//   grid sync: generation-counting atomic (replay-safe, no counter reset).
//   phase 2: blocks grid-stride anchors; positives from smem; per positive
//            warp: cheap mask scan + ballot-compaction, then threefry+gumbel
//            only on compacted candidates (~2 passes instead of 12 tiles).
//   last-done block writes out[0] and swaps accumulators back to zero.
// ---------------------------------------------------------------------------

#define BB 384
#define DD 256
#define MARGIN 0.2f
#define GRID 144
#define NWARP 8

__device__ float  g_dist[BB * BB];
__device__ double g_total;          // zero-init; each replay returns it to 0
__device__ unsigned int g_count;    // zero-init; each replay returns it to 0
__device__ unsigned int g_arrive;   // monotonically increasing across replays
__device__ unsigned int g_done;     // monotonically increasing across replays

// ---------------- Threefry-2x32-20, key = (0, 42) --------------------------
__device__ __forceinline__ void threefry2x32_42(unsigned c0, unsigned c1,
                                                unsigned& o0, unsigned& o1) {
    const unsigned ks0 = 0u;
    const unsigned ks1 = 42u;
    const unsigned ks2 = 0x1BD11BDAu ^ ks0 ^ ks1;
    unsigned x0 = c0 + ks0;
    unsigned x1 = c1 + ks1;
#define TF_ROUND(R) { x0 += x1; x1 = __funnelshift_l(x1, x1, (R)); x1 ^= x0; }
    TF_ROUND(13) TF_ROUND(15) TF_ROUND(26) TF_ROUND(6)
    x0 += ks1; x1 += ks2 + 1u;
    TF_ROUND(17) TF_ROUND(29) TF_ROUND(16) TF_ROUND(24)
    x0 += ks2; x1 += ks0 + 2u;
    TF_ROUND(13) TF_ROUND(15) TF_ROUND(26) TF_ROUND(6)
    x0 += ks0; x1 += ks1 + 3u;
    TF_ROUND(17) TF_ROUND(29) TF_ROUND(16) TF_ROUND(24)
    x0 += ks1; x1 += ks2 + 4u;
    TF_ROUND(13) TF_ROUND(15) TF_ROUND(26) TF_ROUND(6)
    x0 += ks2; x1 += ks0 + 5u;
#undef TF_ROUND
    o0 = x0; o1 = x1;
}

// jax uniform(tiny,1): f = bitcast((bits>>9)|0x3f800000)-1; u = max(f,tiny);
// gumbel = -log(-log(u)). Accurate logf (selection-critical near u->1).
__device__ __forceinline__ float gumbel_from_bits(unsigned bits) {
    const float tiny = 1.17549435e-38f;
    float f = __uint_as_float((bits >> 9) | 0x3f800000u) - 1.0f;
    float u = fmaxf(f, tiny);
    return -logf(-logf(u));
}

struct SmemP1 {
    float shA[32][33];
    float shB[32][33];
};
struct SmemP2 {
    float s_d[BB];
    float s_nld[BB];
    int   s_lab[BB];
    int   s_pos[BB];
    int   buf[NWARP][BB];    // per-warp compacted candidate indices
    int   s_np;
};

__global__ __launch_bounds__(256) void triplet_fused(const float* __restrict__ feat,
                                                     const int*   __restrict__ labels,
                                                     const int*   __restrict__ epoch_p,
                                                     float*       __restrict__ out) {
    __shared__ union { SmemP1 p1; SmemP2 p2; } sm;
    const int t    = threadIdx.x;
    const int wid  = t >> 5;
    const int lane = t & 31;

    // ---------------- phase 1: dist tile (32x32, 2x2 micro-tiles) ----------
    {
        const int bx = blockIdx.x % 12, by = blockIdx.x / 12;
        const int tx = t & 15, ty = t >> 4;
        const int i0 = by * 32, j0 = bx * 32;
        const int lr = t >> 3;
        const int lc = (t & 7) * 4;
        float a00 = 0.f, a01 = 0.f, a10 = 0.f, a11 = 0.f;

        for (int d0 = 0; d0 < DD; d0 += 32) {
            const float4 av = *(const float4*)&feat[(i0 + lr) * DD + d0 + lc];
            const float4 bv = *(const float4*)&feat[(j0 + lr) * DD + d0 + lc];
            sm.p1.shA[lr][lc + 0] = av.x; sm.p1.shA[lr][lc + 1] = av.y;
            sm.p1.shA[lr][lc + 2] = av.z; sm.p1.shA[lr][lc + 3] = av.w;
            sm.p1.shB[lr][lc + 0] = bv.x; sm.p1.shB[lr][lc + 1] = bv.y;
            sm.p1.shB[lr][lc + 2] = bv.z; sm.p1.shB[lr][lc + 3] = bv.w;
            __syncthreads();
#pragma unroll
            for (int kk = 0; kk < 32; ++kk) {
                const float ai0 = sm.p1.shA[2 * ty + 0][kk];
                const float ai1 = sm.p1.shA[2 * ty + 1][kk];
                const float bj0 = sm.p1.shB[2 * tx + 0][kk];
                const float bj1 = sm.p1.shB[2 * tx + 1][kk];
                float d;
                d = ai0 - bj0; a00 = fmaf(d, d, a00);
                d = ai0 - bj1; a01 = fmaf(d, d, a01);
                d = ai1 - bj0; a10 = fmaf(d, d, a10);
                d = ai1 - bj1; a11 = fmaf(d, d, a11);
            }
            __syncthreads();
        }
        const int i = i0 + 2 * ty;
        const int j = j0 + 2 * tx;
        g_dist[(i + 0) * BB + j + 0] = sqrtf(fmaxf(a00, 1e-11f));
        g_dist[(i + 0) * BB + j + 1] = sqrtf(fmaxf(a01, 1e-11f));
        g_dist[(i + 1) * BB + j + 0] = sqrtf(fmaxf(a10, 1e-11f));
        g_dist[(i + 1) * BB + j + 1] = sqrtf(fmaxf(a11, 1e-11f));
    }

    // ---------------- grid sync (generation counter; replay-safe) ----------
    __syncthreads();
    if (t == 0) {
        __threadfence();
        unsigned old = atomicAdd(&g_arrive, 1u);
        unsigned target = (old / (unsigned)GRID + 1u) * (unsigned)GRID;
        while (atomicAdd(&g_arrive, 0u) < target) __nanosleep(32);
        __threadfence();
    }
    __syncthreads();

    // ---------------- phase 2: mining, grid-strided anchors ----------------
    const bool semiMode = (*epoch_p) > 3;
    // labels are anchor-independent: load once
    for (int k = t; k < BB; k += 256) sm.p2.s_lab[k] = labels[k];
    __syncthreads();

    for (int i = blockIdx.x; i < BB; i += GRID) {
        __syncthreads();                    // protect smem reuse across anchors
        if (t == 0) sm.p2.s_np = 0;
        __syncthreads();
        const int labi = sm.p2.s_lab[i];
        for (int k = t; k < BB; k += 256) {
            if (k > i && sm.p2.s_lab[k] == labi) {
                int slot = atomicAdd(&sm.p2.s_np, 1);
                sm.p2.s_pos[slot] = k;      // order irrelevant: results summed
            }
        }
        __syncthreads();
        const int np = sm.p2.s_np;
        if (np == 0) continue;

        for (int k = t; k < BB; k += 256) {
            float dv = g_dist[i * BB + k];
            sm.p2.s_d[k]   = dv;
            sm.p2.s_nld[k] = -logf(dv);
        }
        __syncthreads();

        for (int w = wid; w < np; w += NWARP) {
            const int   p   = sm.p2.s_pos[w];
            const float dp  = sm.p2.s_d[p];
            const float dhi = dp + MARGIN;
            const unsigned nbase = ((unsigned)i * BB + (unsigned)p) * (unsigned)BB;

            // -- scan + ballot compaction (cheap; no cipher/log here) --------
            int cnt = 0;
#pragma unroll
            for (int tile = 0; tile < BB / 32; ++tile) {
                const int   k  = tile * 32 + lane;
                const float dk = sm.p2.s_d[k];
                bool s;
                if (semiMode) s = (sm.p2.s_lab[k] != labi) && (dk > dp) && (dk < dhi);
                else          s = (sm.p2.s_lab[k] != labi);
                const unsigned bal = __ballot_sync(0xffffffffu, s);
                if (s) {
                    int pos = cnt + __popc(bal & ((1u << lane) - 1u));
                    sm.p2.buf[wid][pos] = k;
                }
                cnt += __popc(bal);
            }

            // -- score only compacted candidates ----------------------------
            // lane-strided ascending k per lane -> strict '>' keeps first max
            float best = -3.4e38f;
            int   bk   = 0;
            for (int base = lane; base < cnt; base += 32) {
                const int k = sm.p2.buf[wid][base];
                unsigned o0, o1;
                threefry2x32_42(0u, nbase + (unsigned)k, o0, o1);
                float sc = (semiMode ? sm.p2.s_nld[k] : 0.0f)
                         + gumbel_from_bits(o0 ^ o1);
                if (sc > best) { best = sc; bk = k; }
            }
            // warp argmax, lowest-index tie-break (matches jnp.argmax)
#pragma unroll
            for (int off = 16; off > 0; off >>= 1) {
                float ov = __shfl_down_sync(0xffffffffu, best, off);
                int   ok = __shfl_down_sync(0xffffffffu, bk,   off);
                if (ov > best || (ov == best && ok < bk)) { best = ov; bk = ok; }
            }
            if (lane == 0 && cnt > 0) {
                float pp = fmaxf(dp - sm.p2.s_d[bk] + MARGIN, 0.0f);
                atomicAdd(&g_total, (double)pp);
                atomicAdd(&g_count, 1u);
            }
        }
    }

    // ---------------- last-done block emits scalar and re-zeros state ------
    __syncthreads();
    if (t == 0) {
        __threadfence();
        unsigned old = atomicAdd(&g_done, 1u);
        if ((old % (unsigned)GRID) == (unsigned)GRID - 1u) {
            unsigned long long tb =
                atomicExch((unsigned long long*)&g_total, 0ull);
            double   tot = __longlong_as_double((long long)tb);
            unsigned cnt = atomicExch(&g_count, 0u);
            out[0] = (cnt > 0u) ? (float)(tot / (double)cnt) : 0.0f;
        }
    }
}

extern "C" void kernel_launch(void* const* d_in, const int* in_sizes, int n_in,
                              void* d_out, int out_size) {
    const float* feat   = (const float*)d_in[0];
    const int*   labels = (const int*)d_in[1];
    const int*   epoch  = (const int*)d_in[2];
    float*       out    = (float*)d_out;

    triplet_fused<<<GRID, 256>>>(feat, labels, epoch, out);
}